// round 2
// baseline (speedup 1.0000x reference)
#include <cuda_runtime.h>
#include <math.h>

// Fixed problem geometry (from setup_inputs): D=128, H=8, PAGE_SIZE=16.
#define DD      128
#define HH      8
#define PAGE    16
#define BUDGET  4096
#define SINK    4
#define VEC_PER_ROW (DD/4)          // 32 float4 per head-row
#define VEC_PER_POS (HH*DD/4)       // 256 float4 per (b,pos) row

// inv_freq[i] = 10000^(-i/64), computed once in double for accuracy.
__device__ float g_invfreq[DD/2];

__global__ void init_invfreq_kernel() {
    int i = threadIdx.x;
    if (i < DD/2) g_invfreq[i] = (float)pow(10000.0, -(double)i / (double)(DD/2));
}

// One thread = one 16-float chunk (4x float4) of a head row.
// Chunk layout within a head row (128 floats): chunks 0-3 = lower RoPE half,
// chunks 4-7 = upper half. 8 threads per head row.
__global__ __launch_bounds__(256)
void skv_kernel(const float4* __restrict__ cache,   // (pages, 2, 16, H, D) fp32
                const float4* __restrict__ knew,    // (bsz, seq_len, H, D)
                const float4* __restrict__ vnew,    // (bsz, seq_len, H, D)
                const int*    __restrict__ qlens,   // (bsz,)
                const int*    __restrict__ ctxp,    // scalar context_len
                float4*       __restrict__ out,     // same layout as cache
                int maxkv, int seq_len, int nchunks)
{
    int t = blockIdx.x * 256 + threadIdx.x;   // chunk index
    if (t >= nchunks) return;

    // Decompose: (page, kv, in_page, h, chunk)
    int c    = t & 7;               // 16-float chunk within head row
    int h    = (t >> 3) & (HH - 1);
    int ip   = (t >> 6) & (PAGE - 1);
    int kv   = (t >> 10) & 1;
    int page = t >> 11;

    int g = page * PAGE + ip;       // global position across batches
    int b = g / maxkv;
    int p = g - b * maxkv;

    int ctx = *ctxp;
    int ql  = __ldg(&qlens[b]);
    bool active  = (ql > 0);
    bool rolling = active && (ctx + ql >  BUDGET);
    bool plain   = active && (ctx + ql <= BUDGET);

    // ---- resolve source head-row pointer (uniform per warp) ----
    const float4* row;
    if (rolling && p >= SINK && p < BUDGET - ql) {
        // shifted read from the cache itself
        int srs = min(ctx, BUDGET) - (BUDGET - ql - SINK);
        int pos = p + srs - SINK;
        pos = min(max(pos, 0), maxkv - 1);
        int gp = b * maxkv + pos;
        row = cache + (size_t)(((gp >> 4) * 2 + kv) * PAGE + (gp & 15)) * VEC_PER_POS
                    + h * VEC_PER_ROW;
    } else if ((rolling && p >= BUDGET - ql && p < BUDGET) ||
               (plain   && p >= ctx         && p < ctx + ql)) {
        // appended new tokens from k/v
        int sp = rolling ? (p - (BUDGET - ql)) : (p - ctx);
        sp = min(max(sp, 0), seq_len - 1);
        const float4* base = kv ? vnew : knew;
        row = base + ((size_t)(b * seq_len + sp) * HH + h) * VEC_PER_ROW;
    } else {
        // plain copy from cache
        int gp = b * maxkv + p;
        row = cache + (size_t)(((gp >> 4) * 2 + kv) * PAGE + (gp & 15)) * VEC_PER_POS
                    + h * VEC_PER_ROW;
    }

    float4* o = out + (size_t)t * 4;

    if (kv == 0 && p < BUDGET) {
        // ---- RoPE on keys, positions [0, BUDGET) ----
        bool lower = (c < 4);
        int cl = lower ? c : (c - 4);         // chunk index within lower half
        int i0 = cl * 16;                     // first freq index of this chunk

        // Batch all 8 loads first -> MLP 8 for latency hiding.
        float4 x1[4], x2[4];
        #pragma unroll
        for (int j = 0; j < 4; j++) {
            x1[j] = row[cl * 4 + j];          // lower-half data
            x2[j] = row[cl * 4 + 16 + j];     // upper-half data
        }

        float fp = (float)p;
        #pragma unroll
        for (int j = 0; j < 4; j++) {
            const float* a = (const float*)&x1[j];
            const float* bb = (const float*)&x2[j];
            float4 r;
            float* rf = (float*)&r;
            #pragma unroll
            for (int kk = 0; kk < 4; kk++) {
                float s, cc;
                sincosf(fp * g_invfreq[i0 + j * 4 + kk], &s, &cc);
                rf[kk] = lower ? (a[kk] * cc - bb[kk] * s)
                               : (a[kk] * s  + bb[kk] * cc);
            }
            o[j] = r;
        }
    } else {
        // values, and keys at p >= BUDGET: straight 64B copy (MLP 4)
        float4 v0 = __ldg(&row[c * 4 + 0]);
        float4 v1 = __ldg(&row[c * 4 + 1]);
        float4 v2 = __ldg(&row[c * 4 + 2]);
        float4 v3 = __ldg(&row[c * 4 + 3]);
        o[0] = v0; o[1] = v1; o[2] = v2; o[3] = v3;
    }
}

extern "C" void kernel_launch(void* const* d_in, const int* in_sizes, int n_in,
                              void* d_out, int out_size) {
    const float4* cache = (const float4*)d_in[0];
    const float4* knew  = (const float4*)d_in[1];
    const float4* vnew  = (const float4*)d_in[2];
    const int*    qlens = (const int*)d_in[3];
    const int*    ctxp  = (const int*)d_in[5];   // context_len scalar (device)

    int bsz = in_sizes[3];                                  // len(query_lens)
    int total_pos = in_sizes[0] / (2 * HH * DD);            // positions across batches
    int maxkv = total_pos / bsz;                            // 8192
    int seq_len = in_sizes[1] / (bsz * HH * DD);            // 2048

    int nchunks = out_size / 16;                            // 16-float chunks
    int blocks = (nchunks + 255) / 256;

    init_invfreq_kernel<<<1, 64>>>();
    skv_kernel<<<blocks, 256>>>(cache, knew, vnew, qlens, ctxp,
                                (float4*)d_out, maxkv, seq_len, nchunks);
}

// round 3
// speedup vs baseline: 1.0907x; 1.0907x over previous
#include <cuda_runtime.h>
#include <math.h>

// Fixed geometry: D=128, H=8, PAGE_SIZE=16, STREAMING_BUDGET=4096, NUM_SINK=4.
#define DD      128
#define HH      8
#define PAGE    16
#define BUDGET  4096
#define SINK    4
#define VEC_PER_ROW (DD/4)            // 32 float4 per head-row
#define F4_PER_PAGE (2*PAGE*HH*DD/4)  // 8192 float4 per page (k half then v half)

__device__ float g_invfreq[DD/2];

__global__ void init_invfreq_kernel() {
    int i = threadIdx.x;
    if (i < DD/2) g_invfreq[i] = (float)pow(10000.0, -(double)i / (double)(DD/2));
}

// Source head-row pointer for the streaming-gather (kv = 0 keys / 1 values).
__device__ __forceinline__ const float4*
resolve_row(const float4* __restrict__ cache, const float4* __restrict__ fresh,
            int b, int p, int kv, int ctx, int ql, int maxkv, int seq_len)
{
    bool active  = (ql > 0);
    bool rolling = active && (ctx + ql >  BUDGET);
    bool plain   = active && (ctx + ql <= BUDGET);

    if (rolling && p >= SINK && p < BUDGET - ql) {
        int srs = min(ctx, BUDGET) - (BUDGET - ql - SINK);
        int pos = min(max(p + srs - SINK, 0), maxkv - 1);
        int gp  = b * maxkv + pos;
        return cache + (size_t)(gp >> 4) * F4_PER_PAGE
                     + (size_t)(kv * PAGE + (gp & 15)) * (HH * VEC_PER_ROW);
    }
    if ((rolling && p >= BUDGET - ql && p < BUDGET) ||
        (plain   && p >= ctx         && p < ctx + ql)) {
        int sp = rolling ? (p - (BUDGET - ql)) : (p - ctx);
        sp = min(max(sp, 0), seq_len - 1);
        return fresh + ((size_t)(b * seq_len + sp) * HH) * VEC_PER_ROW;
    }
    int gp = b * maxkv + p;
    return cache + (size_t)(gp >> 4) * F4_PER_PAGE
                 + (size_t)(kv * PAGE + (gp & 15)) * (HH * VEC_PER_ROW);
}

// Destination float4 base of head-row (b,p,kv) in the paged output.
__device__ __forceinline__ size_t out_row_base(int b, int p, int kv, int maxkv)
{
    int gp = b * maxkv + p;
    return (size_t)(gp >> 4) * F4_PER_PAGE
         + (size_t)(kv * PAGE + (gp & 15)) * (HH * VEC_PER_ROW);
}

// ---------------- Kernel A: RoPE'd keys, p in [0, BUDGET) ----------------
// Thread = one float4 PAIR (d4, d4+16): loads each source float4 exactly once,
// computes sincos once, writes both rotated halves. 16 threads per head row.
__global__ __launch_bounds__(256)
void rope_kernel(const float4* __restrict__ cache,
                 const float4* __restrict__ knew,
                 const int*    __restrict__ qlens,
                 const int*    __restrict__ ctxp,
                 float4*       __restrict__ out,
                 int maxkv, int seq_len, int ntot)
{
    int t = blockIdx.x * 256 + threadIdx.x;
    if (t >= ntot) return;

    int d4 = t & 15;                 // lower-half float4 index (0..15)
    int h  = (t >> 4) & (HH - 1);
    int p  = (t >> 7) & (BUDGET - 1);
    int b  = t >> 19;

    int ctx = *ctxp;
    int ql  = __ldg(&qlens[b]);

    const float4* row = resolve_row(cache, knew, b, p, 0, ctx, ql, maxkv, seq_len)
                        + h * VEC_PER_ROW;
    float4 x1 = __ldg(&row[d4]);
    float4 x2 = __ldg(&row[d4 + 16]);

    float fp = (float)p;
    int i0 = d4 * 4;
    float4 lo, hi;
    const float* a  = (const float*)&x1;
    const float* bb = (const float*)&x2;
    float* lf = (float*)&lo;
    float* hf = (float*)&hi;
    #pragma unroll
    for (int j = 0; j < 4; j++) {
        float s, c;
        sincosf(fp * g_invfreq[i0 + j], &s, &c);
        lf[j] = a[j] * c - bb[j] * s;
        hf[j] = a[j] * s + bb[j] * c;
    }

    float4* orow = out + out_row_base(b, p, 0, maxkv) + h * VEC_PER_ROW;
    orow[d4]      = lo;
    orow[d4 + 16] = hi;
}

// ---------------- Kernel B: v-gather (p<BUDGET) + identity (p>=BUDGET) ----
// Thread = 2 consecutive float4 (64B). First nv_t threads: value gather.
// Remaining: flat page-aligned copy cache->out (masks all false there).
__global__ __launch_bounds__(256)
void copy_kernel(const float4* __restrict__ cache,
                 const float4* __restrict__ vnew,
                 const int*    __restrict__ qlens,
                 const int*    __restrict__ ctxp,
                 float4*       __restrict__ out,
                 int maxkv, int seq_len,
                 int nv_t, int id_shift, int id_mask,
                 long long id_pairs_base, int ntot)
{
    int t = blockIdx.x * 256 + threadIdx.x;
    if (t >= ntot) return;

    if (t < nv_t) {
        int d4 = (t & 15) * 2;           // pair of consecutive float4
        int h  = (t >> 4) & (HH - 1);
        int p  = (t >> 7) & (BUDGET - 1);
        int b  = t >> 19;

        int ctx = *ctxp;
        int ql  = __ldg(&qlens[b]);
        const float4* row = resolve_row(cache, vnew, b, p, 1, ctx, ql, maxkv, seq_len)
                            + h * VEC_PER_ROW;
        float4 v0 = __ldg(&row[d4]);
        float4 v1 = __ldg(&row[d4 + 1]);
        float4* orow = out + out_row_base(b, p, 1, maxkv) + h * VEC_PER_ROW;
        orow[d4]     = v0;
        orow[d4 + 1] = v1;
    } else {
        // identity region: per batch b, pages [b*ppb + BUDGET/16, (b+1)*ppb)
        long long j = t - nv_t;
        int b   = (int)(j >> id_shift);
        long long off = j & id_mask;                       // pair offset in chunk
        long long base = ((long long)b * (maxkv / PAGE) + (BUDGET / PAGE))
                         * F4_PER_PAGE + id_pairs_base;    // id_pairs_base = 0
        long long idx = base + off * 2;
        float4 v0 = __ldg(&cache[idx]);
        float4 v1 = __ldg(&cache[idx + 1]);
        out[idx]     = v0;
        out[idx + 1] = v1;
    }
}

extern "C" void kernel_launch(void* const* d_in, const int* in_sizes, int n_in,
                              void* d_out, int out_size) {
    const float4* cache = (const float4*)d_in[0];
    const float4* knew  = (const float4*)d_in[1];
    const float4* vnew  = (const float4*)d_in[2];
    const int*    qlens = (const int*)d_in[3];
    const int*    ctxp  = (const int*)d_in[5];   // context_len scalar (device)

    int bsz = in_sizes[3];
    int total_pos = in_sizes[0] / (2 * HH * DD);
    int maxkv = total_pos / bsz;                 // 8192
    int seq_len = in_sizes[1] / (bsz * HH * DD); // 2048

    // Kernel A: one thread per rope float4-pair
    int nA = bsz * BUDGET * HH * (VEC_PER_ROW / 2);          // bsz*4096*8*16

    // Kernel B: v-gather pairs + identity pairs
    int nv_t = bsz * BUDGET * HH * (VEC_PER_ROW / 2);        // 64B units
    int id_pages = maxkv / PAGE - BUDGET / PAGE;             // per batch
    long long id_pairs = (long long)id_pages * F4_PER_PAGE / 2; // pairs per batch
    int id_shift = 0;
    while ((1LL << id_shift) < id_pairs) id_shift++;         // id_pairs is pow2 here
    int id_mask = (int)(id_pairs - 1);
    int ntotB = nv_t + (int)(id_pairs * bsz);

    init_invfreq_kernel<<<1, 64>>>();
    rope_kernel<<<(nA + 255) / 256, 256>>>(cache, knew, qlens, ctxp,
                                           (float4*)d_out, maxkv, seq_len, nA);
    copy_kernel<<<(ntotB + 255) / 256, 256>>>(cache, vnew, qlens, ctxp,
                                              (float4*)d_out, maxkv, seq_len,
                                              nv_t, id_shift, id_mask, 0, ntotB);
}

// round 4
// speedup vs baseline: 1.1091x; 1.0169x over previous
#include <cuda_runtime.h>
#include <math.h>

// Fixed geometry: D=128, H=8, PAGE_SIZE=16, STREAMING_BUDGET=4096, NUM_SINK=4.
#define DD      128
#define HH      8
#define PAGE    16
#define BUDGET  4096
#define SINK    4
#define VEC_PER_ROW (DD/4)            // 32 float4 per head-row
#define F4_PER_PAGE (2*PAGE*HH*DD/4)  // 8192 float4 per page (k half then v half)

// log2(10000)/64, double precision
#define LOG2_1E4_OVER_64 0.20762050593045952

// Source head-row pointer for the streaming-gather (kv = 0 keys / 1 values).
__device__ __forceinline__ const float4*
resolve_row(const float4* __restrict__ cache, const float4* __restrict__ fresh,
            int b, int p, int kv, int ctx, int ql, int maxkv, int seq_len)
{
    bool active  = (ql > 0);
    bool rolling = active && (ctx + ql >  BUDGET);
    bool plain   = active && (ctx + ql <= BUDGET);

    if (rolling && p >= SINK && p < BUDGET - ql) {
        int srs = min(ctx, BUDGET) - (BUDGET - ql - SINK);
        int pos = min(max(p + srs - SINK, 0), maxkv - 1);
        int gp  = b * maxkv + pos;
        return cache + (size_t)(gp >> 4) * F4_PER_PAGE
                     + (size_t)(kv * PAGE + (gp & 15)) * (HH * VEC_PER_ROW);
    }
    if ((rolling && p >= BUDGET - ql && p < BUDGET) ||
        (plain   && p >= ctx         && p < ctx + ql)) {
        int sp = rolling ? (p - (BUDGET - ql)) : (p - ctx);
        sp = min(max(sp, 0), seq_len - 1);
        return fresh + ((size_t)(b * seq_len + sp) * HH) * VEC_PER_ROW;
    }
    int gp = b * maxkv + p;
    return cache + (size_t)(gp >> 4) * F4_PER_PAGE
                 + (size_t)(kv * PAGE + (gp & 15)) * (HH * VEC_PER_ROW);
}

// Destination float4 base of head-row (b,p,kv) in the paged output.
__device__ __forceinline__ size_t out_row_base(int b, int p, int kv, int maxkv)
{
    int gp = b * maxkv + p;
    return (size_t)(gp >> 4) * F4_PER_PAGE
         + (size_t)(kv * PAGE + (gp & 15)) * (HH * VEC_PER_ROW);
}

// Fused single-launch kernel. Flat grid over three regions:
//   [0, nA)        rope'd keys, p<BUDGET. thread = float4 pair (d4, d4+16).
//   [nA, nAV)      value gather, p<BUDGET. thread = 2 consecutive float4.
//   [nAV, ntot)    identity copy, p>=BUDGET (masks all false). 2 float4/thread.
__global__ __launch_bounds__(256)
void skv_fused(const float4* __restrict__ cache,
               const float4* __restrict__ knew,
               const float4* __restrict__ vnew,
               const int*    __restrict__ qlens,
               const int*    __restrict__ ctxp,
               float4*       __restrict__ out,
               int maxkv, int seq_len,
               int nA, int nAV,
               int id_shift, int id_mask, int ntot)
{
    __shared__ float sfreq[DD/2];
    int tid = threadIdx.x;
    int gid = blockIdx.x * 256 + tid;
    int blk0 = blockIdx.x * 256;

    // Blocks overlapping the rope region build the inv_freq table in smem
    // (double exp2 -> correctly-rounded fp32, same values as a double pow).
    if (blk0 < nA) {
        if (tid < DD/2)
            sfreq[tid] = (float)exp2(-(double)tid * LOG2_1E4_OVER_64);
        __syncthreads();
    }

    if (gid >= ntot) return;

    if (gid < nA) {
        // ---- RoPE keys ----
        int d4 = gid & 15;                 // lower-half float4 index (0..15)
        int h  = (gid >> 4) & (HH - 1);
        int p  = (gid >> 7) & (BUDGET - 1);
        int b  = gid >> 19;

        int ctx = *ctxp;
        int ql  = __ldg(&qlens[b]);

        const float4* row = resolve_row(cache, knew, b, p, 0, ctx, ql, maxkv, seq_len)
                            + h * VEC_PER_ROW;
        float4 x1 = __ldg(&row[d4]);
        float4 x2 = __ldg(&row[d4 + 16]);

        float fp = (float)p;
        int i0 = d4 * 4;
        float4 lo, hi;
        const float* a  = (const float*)&x1;
        const float* bb = (const float*)&x2;
        float* lf = (float*)&lo;
        float* hf = (float*)&hi;
        #pragma unroll
        for (int j = 0; j < 4; j++) {
            float s, c;
            sincosf(fp * sfreq[i0 + j], &s, &c);
            lf[j] = a[j] * c - bb[j] * s;
            hf[j] = a[j] * s + bb[j] * c;
        }

        float4* orow = out + out_row_base(b, p, 0, maxkv) + h * VEC_PER_ROW;
        orow[d4]      = lo;
        orow[d4 + 16] = hi;
    } else if (gid < nAV) {
        // ---- value gather, p < BUDGET ----
        int j  = gid - nA;
        int d4 = (j & 15) * 2;             // pair of consecutive float4
        int h  = (j >> 4) & (HH - 1);
        int p  = (j >> 7) & (BUDGET - 1);
        int b  = j >> 19;

        int ctx = *ctxp;
        int ql  = __ldg(&qlens[b]);
        const float4* row = resolve_row(cache, vnew, b, p, 1, ctx, ql, maxkv, seq_len)
                            + h * VEC_PER_ROW;
        float4 v0 = __ldg(&row[d4]);
        float4 v1 = __ldg(&row[d4 + 1]);
        float4* orow = out + out_row_base(b, p, 1, maxkv) + h * VEC_PER_ROW;
        orow[d4]     = v0;
        orow[d4 + 1] = v1;
    } else {
        // ---- identity region: per batch, pages [BUDGET/16, maxkv/16) ----
        int j = gid - nAV;
        int b = j >> id_shift;
        long long off = (long long)(j & id_mask);   // f4-pair offset in chunk
        long long base = ((long long)b * (maxkv / PAGE) + (BUDGET / PAGE))
                         * F4_PER_PAGE;
        long long idx = base + off * 2;
        float4 v0 = __ldg(&cache[idx]);
        float4 v1 = __ldg(&cache[idx + 1]);
        out[idx]     = v0;
        out[idx + 1] = v1;
    }
}

extern "C" void kernel_launch(void* const* d_in, const int* in_sizes, int n_in,
                              void* d_out, int out_size) {
    const float4* cache = (const float4*)d_in[0];
    const float4* knew  = (const float4*)d_in[1];
    const float4* vnew  = (const float4*)d_in[2];
    const int*    qlens = (const int*)d_in[3];
    const int*    ctxp  = (const int*)d_in[5];   // context_len scalar (device)

    int bsz = in_sizes[3];
    int total_pos = in_sizes[0] / (2 * HH * DD);
    int maxkv = total_pos / bsz;                 // 8192
    int seq_len = in_sizes[1] / (bsz * HH * DD); // 2048

    // Region sizes (threads)
    int nA  = bsz * BUDGET * HH * (VEC_PER_ROW / 2);   // rope pairs
    int nV  = bsz * BUDGET * HH * (VEC_PER_ROW / 2);   // value 32B units
    int nAV = nA + nV;

    int id_pages = maxkv / PAGE - BUDGET / PAGE;                 // per batch
    long long id_pairs = (long long)id_pages * F4_PER_PAGE / 2;  // per batch (pow2)
    int id_shift = 0;
    while ((1LL << id_shift) < id_pairs) id_shift++;
    int id_mask = (int)(id_pairs - 1);

    int ntot = nAV + (int)(id_pairs * bsz);
    int blocks = (ntot + 255) / 256;

    skv_fused<<<blocks, 256>>>(cache, knew, vnew, qlens, ctxp,
                               (float4*)d_out, maxkv, seq_len,
                               nA, nAV, id_shift, id_mask, ntot);
}